// round 6
// baseline (speedup 1.0000x reference)
#include <cuda_runtime.h>
#include <cuda_bf16.h>
#include <float.h>

#define BS 16
#define SEQ 512
#define VOCAB 32000
#define NV4 (VOCAB / 4)
#define NMASK 80
#define NITEMS (BS * NMASK)
#define THREADS 256

// Scratch (no device allocation allowed). Zero-initialized at module load.
__device__ float    g_logp[NITEMS];
__device__ int      g_corr[NITEMS];
__device__ unsigned g_done;

__device__ __forceinline__ float max4(float4 q) {
    return fmaxf(fmaxf(q.x, q.y), fmaxf(q.z, q.w));
}

// ---------------------------------------------------------------------------
// One CTA per (b, j) item. Warp 0 prologue: layout detect + ballot-scan to
// find this item's masked position. Main loop: branchless streaming argmax.
// Last-arriving CTA does the deterministic final reduction.
// ---------------------------------------------------------------------------
__global__ __launch_bounds__(THREADS)
void item_kernel(const float* __restrict__ output,
                 const void* __restrict__ target_raw,
                 const void* __restrict__ mask_raw,
                 float* __restrict__ out, int out_size) {
    const int item = blockIdx.x;             // 0..1279
    const int b    = item / NMASK;
    const int j    = item - b * NMASK;
    const int tid  = threadIdx.x;

    __shared__ int   s_pos, s_tgt;
    __shared__ float s_tlogp;
    __shared__ float s_val[THREADS];
    __shared__ int   s_bidx;
    __shared__ int   s_last;

    // ---- warp-0 prologue: layout detection + position recovery ----
    if (tid < 32) {
        const unsigned full = 0xffffffffu;
        const unsigned* mw = (const unsigned*)mask_raw;
        const unsigned* tw = (const unsigned*)target_raw;

        // mask layout: int32-bool words are only 0/1; any other word => bytes
        unsigned viol = 0;
        for (int i = tid; i < 512; i += 32)
            viol |= (mw[i] & ~1u) ? 1u : 0u;
        const bool is_byte = __any_sync(full, viol != 0);

        // target layout: all odd int32 words zero => int64 (targets < 32000)
        unsigned oddnz = 0;
        for (int i = tid; i < 128; i += 32)
            oddnz |= tw[2 * i + 1];
        const bool is_i64 = !__any_sync(full, oddnz != 0);

        // ballot scan over 512 positions of row b -> j-th masked position
        int cnt = 0, pos = -1;
        for (int c = 0; c < SEQ / 32; c++) {
            const int s = c * 32 + tid;
            int m;
            if (is_byte) m = ((const unsigned char*)mask_raw)[(size_t)b * SEQ + s] != 0;
            else         m = ((const int*)mask_raw)[(size_t)b * SEQ + s] != 0;
            unsigned bal = __ballot_sync(full, m);
            int pc = __popc(bal);
            if (j >= cnt && j < cnt + pc)
                pos = c * 32 + __fns(bal, 0, j - cnt + 1);
            cnt += pc;
        }

        if (tid == 0) {
            const int tgt = is_i64
                          ? (int)((const long long*)target_raw)[item]
                          : ((const int*)target_raw)[item];
            s_pos = pos;
            s_tgt = tgt;
            s_tlogp = output[((size_t)b * SEQ + pos) * VOCAB + tgt];
            s_bidx = VOCAB;
        }
    }
    __syncthreads();

    const int pos = s_pos;
    const int tgt = s_tgt;
    const float* __restrict__ rowf = output + ((size_t)b * SEQ + pos) * VOCAB;
    const float4* __restrict__ row = (const float4*)rowf;

    // ---- branchless streaming max (index recovery deferred) ----
    float best = -FLT_MAX;
    int   bno  = 0;     // batch start (float4 index) containing this thread's max

    int v = tid;
    for (; v + 7 * THREADS < NV4; v += 8 * THREADS) {
        float4 q[8];
#pragma unroll
        for (int u = 0; u < 8; u++) q[u] = __ldcs(&row[v + u * THREADS]);
        float m0 = fmaxf(max4(q[0]), max4(q[1]));
        float m1 = fmaxf(max4(q[2]), max4(q[3]));
        float m2 = fmaxf(max4(q[4]), max4(q[5]));
        float m3 = fmaxf(max4(q[6]), max4(q[7]));
        float m  = fmaxf(fmaxf(m0, m1), fmaxf(m2, m3));
        bno  = (m > best) ? v : bno;     // SEL, no branch
        best = fmaxf(best, m);
    }
    for (; v + 3 * THREADS < NV4; v += 4 * THREADS) {
        float4 q[4];
#pragma unroll
        for (int u = 0; u < 4; u++) q[u] = __ldcs(&row[v + u * THREADS]);
        float m = fmaxf(fmaxf(max4(q[0]), max4(q[1])),
                        fmaxf(max4(q[2]), max4(q[3])));
        bno  = (m > best) ? v : bno;
        best = fmaxf(best, m);
    }
    for (; v < NV4; v += THREADS) {
        float4 q = __ldcs(&row[v]);
        float m = max4(q);
        bno  = (m > best) ? v : bno;
        best = fmaxf(best, m);
    }

    // ---- CTA max (value only) ----
    s_val[tid] = best;
    __syncthreads();
    for (int stride = THREADS / 2; stride > 0; stride >>= 1) {
        if (tid < stride) s_val[tid] = fmaxf(s_val[tid], s_val[tid + stride]);
        __syncthreads();
    }
    const float ctamax = s_val[0];

    // ---- index recovery: winners re-scan their winning batch (<=512 B) ----
    if (best == ctamax) {
        int lidx = VOCAB;
#pragma unroll
        for (int u = 7; u >= 0; u--) {
            const int fv = bno + u * THREADS;
            if (fv < NV4) {
                float4 q = row[fv];
                const int base = fv * 4;
                if (q.w == ctamax) lidx = base + 3;
                if (q.z == ctamax) lidx = base + 2;
                if (q.y == ctamax) lidx = base + 1;
                if (q.x == ctamax) lidx = base + 0;
            }
        }
        atomicMin(&s_bidx, lidx);
    }
    __syncthreads();

    if (tid == 0) {
        g_logp[item] = s_tlogp;
        g_corr[item] = (s_bidx == tgt) ? 1 : 0;
        __threadfence();
        s_last = (atomicAdd(&g_done, 1u) == (unsigned)(NITEMS - 1));
    }
    __syncthreads();

    // ---- last-arriving CTA: deterministic final reduction ----
    if (s_last) {
        __threadfence();
        float lsum = 0.0f;
        int   csum = 0;
        for (int i = tid; i < NITEMS; i += THREADS) {
            lsum += g_logp[i];
            csum += g_corr[i];
        }
        s_val[tid] = lsum;
        __shared__ int s_cnt[THREADS];
        s_cnt[tid] = csum;
        __syncthreads();
        for (int stride = THREADS / 2; stride > 0; stride >>= 1) {
            if (tid < stride) {
                s_val[tid] += s_val[tid + stride];
                s_cnt[tid] += s_cnt[tid + stride];
            }
            __syncthreads();
        }
        if (tid == 0) {
            const float inv = 1.0f / (float)NITEMS;
            if (out_size > 0) out[0] = -s_val[0] * inv;
            if (out_size > 1) out[1] = (float)s_cnt[0] * inv;
            g_done = 0;   // reset for next graph replay (deterministic)
        }
    }
}

extern "C" void kernel_launch(void* const* d_in, const int* in_sizes, int n_in,
                              void* d_out, int out_size) {
    const float* output = (const float*)d_in[0];
    const void*  target = d_in[1];
    const void*  mask   = d_in[2];
    float* out = (float*)d_out;

    item_kernel<<<NITEMS, THREADS>>>(output, target, mask, out, out_size);
}

// round 7
// speedup vs baseline: 1.2589x; 1.2589x over previous
#include <cuda_runtime.h>
#include <cuda_bf16.h>
#include <float.h>

#define BS 16
#define SEQ 512
#define VOCAB 32000
#define NV4 (VOCAB / 4)
#define NMASK 80
#define NITEMS (BS * NMASK)
#define THREADS 128

// Scratch (no device allocation allowed)
__device__ int      g_pos[NITEMS];     // masked positions, row-major (b, j)
__device__ float    g_logp[NITEMS];    // log-prob at target per item
__device__ int      g_corr[NITEMS];    // 1 if argmax == target
__device__ int      g_mask_is_byte;
__device__ int      g_tgt_is_i64;
__device__ unsigned g_done;

// ---------------------------------------------------------------------------
// Kernel 1: layout detection + masked-position recovery (ballot scan, one
// warp per batch row; stable ascending order == stable argsort semantics).
// ---------------------------------------------------------------------------
__global__ void prep_kernel(const unsigned char* __restrict__ mask,
                            const int* __restrict__ target32) {
    __shared__ int s_byte, s_odd;
    const int tid = threadIdx.x;
    if (tid == 0) { s_byte = 0; s_odd = 0; g_done = 0; }
    __syncthreads();

    // mask: nonzero byte at offset %4 != 0 => byte-bool layout
    for (int i = tid; i < 2048; i += blockDim.x)
        if ((i & 3) != 0 && mask[i] != 0) atomicOr(&s_byte, 1);
    // target: all odd int32 words zero => int64 layout (targets < 32000)
    for (int i = tid; i < 128; i += blockDim.x)
        if (target32[2 * i + 1] != 0) atomicOr(&s_odd, 1);
    __syncthreads();

    if (tid == 0) {
        g_mask_is_byte = s_byte;
        g_tgt_is_i64   = s_odd ? 0 : 1;
    }

    const int w    = tid >> 5;   // warp -> batch row
    const int lane = tid & 31;
    if (w < BS) {
        const int is_byte = s_byte;
        int cnt = 0;
        for (int c = 0; c < SEQ / 32; c++) {
            const int s = c * 32 + lane;
            int m;
            if (is_byte) m = mask[(size_t)w * SEQ + s] != 0;
            else         m = ((const int*)mask)[(size_t)w * SEQ + s] != 0;
            unsigned bal = __ballot_sync(0xffffffffu, m);
            int pre = cnt + __popc(bal & ((1u << lane) - 1u));
            if (m && pre < NMASK) g_pos[w * NMASK + pre] = s;
            cnt += __popc(bal);
        }
    }
}

__device__ __forceinline__ float max4(float4 q) {
    return fmaxf(fmaxf(q.x, q.y), fmaxf(q.z, q.w));
}

// ---------------------------------------------------------------------------
// Kernel 2: one 128-thread CTA per (b, j) item (10 CTAs/SM -> single wave).
// 8-deep float4 streaming; branchy lowest-index argmax update (keeps 8 loads
// live in registers => MLP=8). Last-arriving CTA reduces.
// ---------------------------------------------------------------------------
__global__ __launch_bounds__(THREADS)
void item_kernel(const float* __restrict__ output,
                 const void* __restrict__ target_raw,
                 float* __restrict__ out, int out_size) {
    const int item = blockIdx.x;            // 0..1279
    const int b    = item / NMASK;
    const int pos  = g_pos[item];
    const int tgt  = g_tgt_is_i64
                   ? (int)((const long long*)target_raw)[item]
                   : ((const int*)target_raw)[item];

    const float* __restrict__ rowf = output + ((size_t)b * SEQ + pos) * VOCAB;
    const float4* __restrict__ row = (const float4*)rowf;

    __shared__ float s_tlogp;
    __shared__ float s_val[THREADS];
    __shared__ int   s_idx[THREADS];
    __shared__ int   s_last;

    const int tid = threadIdx.x;
    if (tid == 0) s_tlogp = __ldg(rowf + tgt);   // direct target gather

    float best = -FLT_MAX;
    int   bidx = VOCAB;

    int v = tid;
    // main: 8 independent float4 loads per iteration (MLP=8)
    for (; v + 7 * THREADS < NV4; v += 8 * THREADS) {
        float4 q[8];
#pragma unroll
        for (int u = 0; u < 8; u++) q[u] = __ldcs(&row[v + u * THREADS]);

        float m0 = fmaxf(max4(q[0]), max4(q[1]));
        float m1 = fmaxf(max4(q[2]), max4(q[3]));
        float m2 = fmaxf(max4(q[4]), max4(q[5]));
        float m3 = fmaxf(max4(q[6]), max4(q[7]));
        float m  = fmaxf(fmaxf(m0, m1), fmaxf(m2, m3));

        if (m > best) {      // rare (~ln of #batches per thread)
            best = m;
#pragma unroll
            for (int u = 7; u >= 0; u--) {   // descending: lowest index wins
                int base = (v + u * THREADS) * 4;
                if (q[u].w == m) bidx = base + 3;
                if (q[u].z == m) bidx = base + 2;
                if (q[u].y == m) bidx = base + 1;
                if (q[u].x == m) bidx = base + 0;
            }
        }
    }
    // mid: 4-deep
    for (; v + 3 * THREADS < NV4; v += 4 * THREADS) {
        float4 q[4];
#pragma unroll
        for (int u = 0; u < 4; u++) q[u] = __ldcs(&row[v + u * THREADS]);
        float m = fmaxf(fmaxf(max4(q[0]), max4(q[1])),
                        fmaxf(max4(q[2]), max4(q[3])));
        if (m > best) {
            best = m;
#pragma unroll
            for (int u = 3; u >= 0; u--) {
                int base = (v + u * THREADS) * 4;
                if (q[u].w == m) bidx = base + 3;
                if (q[u].z == m) bidx = base + 2;
                if (q[u].y == m) bidx = base + 1;
                if (q[u].x == m) bidx = base + 0;
            }
        }
    }
    // tail
    for (; v < NV4; v += THREADS) {
        float4 q = __ldcs(&row[v]);
        float m = max4(q);
        if (m > best) {
            best = m;
            int base = v * 4;
            if (q.w == m) bidx = base + 3;
            if (q.z == m) bidx = base + 2;
            if (q.y == m) bidx = base + 1;
            if (q.x == m) bidx = base + 0;
        }
    }

    s_val[tid] = best;
    s_idx[tid] = bidx;
    __syncthreads();

    // tree reduction; tie-break: lower index wins
    for (int stride = THREADS / 2; stride > 0; stride >>= 1) {
        if (tid < stride) {
            float v2 = s_val[tid + stride];
            int   i2 = s_idx[tid + stride];
            if (v2 > s_val[tid] || (v2 == s_val[tid] && i2 < s_idx[tid])) {
                s_val[tid] = v2;
                s_idx[tid] = i2;
            }
        }
        __syncthreads();
    }

    if (tid == 0) {
        g_logp[item] = s_tlogp;
        g_corr[item] = (s_idx[0] == tgt) ? 1 : 0;
        __threadfence();
        s_last = (atomicAdd(&g_done, 1u) == (unsigned)(NITEMS - 1));
    }
    __syncthreads();

    // last-arriving CTA: deterministic final reduction
    if (s_last) {
        __threadfence();
        float lsum = 0.0f;
        int   csum = 0;
        for (int i = tid; i < NITEMS; i += THREADS) {
            lsum += g_logp[i];
            csum += g_corr[i];
        }
        s_val[tid] = lsum;
        s_idx[tid] = csum;
        __syncthreads();
        for (int stride = THREADS / 2; stride > 0; stride >>= 1) {
            if (tid < stride) {
                s_val[tid] += s_val[tid + stride];
                s_idx[tid] += s_idx[tid + stride];
            }
            __syncthreads();
        }
        if (tid == 0) {
            const float inv = 1.0f / (float)NITEMS;
            if (out_size > 0) out[0] = -s_val[0] * inv;
            if (out_size > 1) out[1] = (float)s_idx[0] * inv;
        }
    }
}

extern "C" void kernel_launch(void* const* d_in, const int* in_sizes, int n_in,
                              void* d_out, int out_size) {
    const float* output = (const float*)d_in[0];
    const void*  target = d_in[1];
    const void*  mask   = d_in[2];
    float* out = (float*)d_out;

    prep_kernel<<<1, 512>>>((const unsigned char*)mask, (const int*)target);
    item_kernel<<<NITEMS, THREADS>>>(output, target, out, out_size);
}